// round 7
// baseline (speedup 1.0000x reference)
#include <cuda_runtime.h>
#include <cuda_fp16.h>

#define NB 2048
#define NF 4096
#define NC 8192
#define NT 8
#define NK 1024
#define NS 8
#define MB 8            // batch rows per CTA (fp16, 8 rows per 16B slot)
#define THREADS 512     // 2 k-values per thread -> 128-reg budget

// 16-bit slot table, layout [s][k][t]: index = (s*NK + k)*NT + t.
// slot = feat*2 + (sign>0 ? 0 : 1); smem byte addr = slot*16.
__device__ unsigned short g_slot[NS * NK * NT];   // 128 KB

__global__ void prep_kernel(const int* __restrict__ conj_feat,
                            const int* __restrict__ conj_sign,
                            const int* __restrict__ class_conj) {
    int i = blockIdx.x * blockDim.x + threadIdx.x;
    if (i >= NK * NS * NT) return;
    int k = i >> 6;
    int j = i & 63;
    int s = j >> 3;
    int t = j & 7;
    int c    = class_conj[k * NS + s];
    int feat = conj_feat[c * NT + t];
    int sign = conj_sign[c * NT + t];
    g_slot[(s * NK + k) * NT + t] = (unsigned short)(feat * 2 + (sign > 0 ? 0 : 1));
}

static __device__ __forceinline__ unsigned hmul2u(unsigned a, unsigned b) {
    __half2 ha = *reinterpret_cast<__half2*>(&a);
    __half2 hb = *reinterpret_cast<__half2*>(&b);
    __half2 hr = __hmul2(ha, hb);
    return *reinterpret_cast<unsigned*>(&hr);
}
static __device__ __forceinline__ unsigned hmax2u(unsigned a, unsigned b) {
    __half2 ha = *reinterpret_cast<__half2*>(&a);
    __half2 hb = *reinterpret_cast<__half2*>(&b);
    __half2 hr = __hmax2(ha, hb);
    return *reinterpret_cast<unsigned*>(&hr);
}
static __device__ __forceinline__ uint4 mulh8(uint4 a, uint4 b) {
    a.x = hmul2u(a.x, b.x); a.y = hmul2u(a.y, b.y);
    a.z = hmul2u(a.z, b.z); a.w = hmul2u(a.w, b.w);
    return a;
}
static __device__ __forceinline__ uint4 maxh8(uint4 a, uint4 b) {
    a.x = hmax2u(a.x, b.x); a.y = hmax2u(a.y, b.y);
    a.z = hmax2u(a.z, b.z); a.w = hmax2u(a.w, b.w);
    return a;
}
static __device__ __forceinline__ unsigned pack2(float a, float b) {
    __half2 h = __floats2half2_rn(a, b);
    return *reinterpret_cast<unsigned*>(&h);
}

// gather 8 slots for one s-group table entry and reduce to product
static __device__ __forceinline__ uint4 sgroup(const char* sb, uint4 t) {
    uint4 q0 = *(const uint4*)(sb + ((t.x & 0xFFFFu) << 4));
    uint4 q1 = *(const uint4*)(sb + ((t.x >> 16)     << 4));
    uint4 q2 = *(const uint4*)(sb + ((t.y & 0xFFFFu) << 4));
    uint4 q3 = *(const uint4*)(sb + ((t.y >> 16)     << 4));
    uint4 q4 = *(const uint4*)(sb + ((t.z & 0xFFFFu) << 4));
    uint4 q5 = *(const uint4*)(sb + ((t.z >> 16)     << 4));
    uint4 q6 = *(const uint4*)(sb + ((t.w & 0xFFFFu) << 4));
    uint4 q7 = *(const uint4*)(sb + ((t.w >> 16)     << 4));
    return mulh8(mulh8(mulh8(q0, q1), mulh8(q2, q3)),
                 mulh8(mulh8(q4, q5), mulh8(q6, q7)));
}

static __device__ __forceinline__ void store_k(float* out, int b0, int k, uint4 mx) {
    float2 r01 = __half22float2(*reinterpret_cast<__half2*>(&mx.x));
    float2 r23 = __half22float2(*reinterpret_cast<__half2*>(&mx.y));
    float2 r45 = __half22float2(*reinterpret_cast<__half2*>(&mx.z));
    float2 r67 = __half22float2(*reinterpret_cast<__half2*>(&mx.w));
    out[(size_t)(b0 + 0) * NK + k] = r01.x;
    out[(size_t)(b0 + 1) * NK + k] = r01.y;
    out[(size_t)(b0 + 2) * NK + k] = r23.x;
    out[(size_t)(b0 + 3) * NK + k] = r23.y;
    out[(size_t)(b0 + 4) * NK + k] = r45.x;
    out[(size_t)(b0 + 5) * NK + k] = r45.y;
    out[(size_t)(b0 + 6) * NK + k] = r67.x;
    out[(size_t)(b0 + 7) * NK + k] = r67.y;
}

__global__ void __launch_bounds__(THREADS, 1)
dnf_kernel(const float* __restrict__ x, float* __restrict__ out) {
    extern __shared__ unsigned smem_u[];   // [4096 feat][2 var][4 x u32] = 128 KB
    const int b0 = blockIdx.x * MB;

    // Phase A: build 16B slots, conflict-free STS.128, coalesced LDG.
    uint4* slots = (uint4*)smem_u;
    for (int f = threadIdx.x; f < NF; f += THREADS) {
        float v[MB];
        #pragma unroll
        for (int r = 0; r < MB; r++)
            v[r] = x[(size_t)(b0 + r) * NF + f];
        uint4 hx, hn;
        hx.x = pack2(v[0], v[1]);               hn.x = pack2(1.f - v[0], 1.f - v[1]);
        hx.y = pack2(v[2], v[3]);               hn.y = pack2(1.f - v[2], 1.f - v[3]);
        hx.z = pack2(v[4], v[5]);               hn.z = pack2(1.f - v[4], 1.f - v[5]);
        hx.w = pack2(v[6], v[7]);               hn.w = pack2(1.f - v[6], 1.f - v[7]);
        slots[f * 2]     = hx;
        slots[f * 2 + 1] = hn;
    }
    __syncthreads();

    const char* sb = (const char*)smem_u;
    const int k0 = threadIdx.x;            // stream 0
    const int k1 = threadIdx.x + THREADS;  // stream 1 (independent)
    const uint4* tab0 = (const uint4*)g_slot + k0;
    const uint4* tab1 = (const uint4*)g_slot + k1;

    uint4 ta0 = tab0[0];
    uint4 ta1 = tab1[0];
    uint4 mx0 = make_uint4(0u, 0u, 0u, 0u);
    uint4 mx1 = make_uint4(0u, 0u, 0u, 0u);

    #pragma unroll
    for (int s = 0; s < NS; s++) {
        uint4 tn0, tn1;
        if (s < NS - 1) {
            tn0 = tab0[(s + 1) * NK];      // prefetch next s for both streams
            tn1 = tab1[(s + 1) * NK];
        }
        uint4 p0 = sgroup(sb, ta0);
        uint4 p1 = sgroup(sb, ta1);
        mx0 = maxh8(mx0, p0);
        mx1 = maxh8(mx1, p1);
        if (s < NS - 1) { ta0 = tn0; ta1 = tn1; }
    }

    store_k(out, b0, k0, mx0);
    store_k(out, b0, k1, mx1);
}

extern "C" void kernel_launch(void* const* d_in, const int* in_sizes, int n_in,
                              void* d_out, int out_size) {
    const float* x  = (const float*)d_in[0];
    const int*   cf = (const int*)d_in[1];
    const int*   cs = (const int*)d_in[2];
    const int*   cc = (const int*)d_in[3];
    float* out = (float*)d_out;

    prep_kernel<<<(NK * NS * NT + 255) / 256, 256>>>(cf, cs, cc);

    size_t smem_bytes = (size_t)NF * 2 * MB * sizeof(__half);  // 131072
    cudaFuncSetAttribute(dnf_kernel,
                         cudaFuncAttributeMaxDynamicSharedMemorySize,
                         (int)smem_bytes);
    dnf_kernel<<<NB / MB, THREADS, smem_bytes>>>(x, out);
}